// round 1
// baseline (speedup 1.0000x reference)
#include <cuda_runtime.h>
#include <math.h>

#define BATCH 2
#define SEQ   2048
#define HID   2048
#define NHEAD 16
#define HDIM  128
#define FFD   8192
#define ROWS  (BATCH*SEQ)   // 4096

// ---------------- scratch (static device allocations are allowed) ----------
__device__ float g_xn[ROWS*HID];
__device__ float g_q [ROWS*HID];
__device__ float g_k [ROWS*HID];
__device__ float g_v [ROWS*HID];
__device__ float g_att[ROWS*HID];
__device__ float g_h [ROWS*HID];
__device__ float g_hn[ROWS*HID];
__device__ float g_ff[(size_t)ROWS*FFD];

// ---------------- LayerNorm: one block (256 thr) per row of 2048 -----------
__global__ void ln_kernel(const float* __restrict__ x,
                          const float* __restrict__ g,
                          const float* __restrict__ b,
                          float* __restrict__ out)
{
    const int row = blockIdx.x;
    const int tid = threadIdx.x;              // 256
    const float* xr = x + (size_t)row * HID;
    float* orow = out + (size_t)row * HID;

    float4 v0 = reinterpret_cast<const float4*>(xr)[tid];
    float4 v1 = reinterpret_cast<const float4*>(xr)[tid + 256];

    __shared__ float red[8];

    float s = v0.x+v0.y+v0.z+v0.w + v1.x+v1.y+v1.z+v1.w;
    #pragma unroll
    for (int o = 16; o > 0; o >>= 1) s += __shfl_xor_sync(0xffffffffu, s, o);
    if ((tid & 31) == 0) red[tid >> 5] = s;
    __syncthreads();
    float mu = (red[0]+red[1]+red[2]+red[3]+red[4]+red[5]+red[6]+red[7]) * (1.0f/HID);
    __syncthreads();

    float d0x=v0.x-mu, d0y=v0.y-mu, d0z=v0.z-mu, d0w=v0.w-mu;
    float d1x=v1.x-mu, d1y=v1.y-mu, d1z=v1.z-mu, d1w=v1.w-mu;
    float sq = d0x*d0x+d0y*d0y+d0z*d0z+d0w*d0w + d1x*d1x+d1y*d1y+d1z*d1z+d1w*d1w;
    #pragma unroll
    for (int o = 16; o > 0; o >>= 1) sq += __shfl_xor_sync(0xffffffffu, sq, o);
    if ((tid & 31) == 0) red[tid >> 5] = sq;
    __syncthreads();
    float var = (red[0]+red[1]+red[2]+red[3]+red[4]+red[5]+red[6]+red[7]) * (1.0f/HID);
    float rstd = rsqrtf(var + 1e-5f);

    int c0 = tid * 4;
    int c1 = (tid + 256) * 4;
    float4 g0 = reinterpret_cast<const float4*>(g)[tid];
    float4 g1 = reinterpret_cast<const float4*>(g)[tid + 256];
    float4 b0 = reinterpret_cast<const float4*>(b)[tid];
    float4 b1 = reinterpret_cast<const float4*>(b)[tid + 256];
    float4 o0, o1;
    o0.x = d0x*rstd*g0.x + b0.x;  o0.y = d0y*rstd*g0.y + b0.y;
    o0.z = d0z*rstd*g0.z + b0.z;  o0.w = d0w*rstd*g0.w + b0.w;
    o1.x = d1x*rstd*g1.x + b1.x;  o1.y = d1y*rstd*g1.y + b1.y;
    o1.z = d1z*rstd*g1.z + b1.z;  o1.w = d1w*rstd*g1.w + b1.w;
    *reinterpret_cast<float4*>(orow + c0) = o0;
    *reinterpret_cast<float4*>(orow + c1) = o1;
}

// ---------------- SGEMM 128x128x8, 256 threads, 8x8 per thread -------------
// ACT: 0 = none, 1 = residual add, 2 = tanh-GELU
__device__ __forceinline__ float gelu_tanh(float x) {
    float x3 = x * x * x;
    float t  = tanhf(0.7978845608028654f * (x + 0.044715f * x3));
    return 0.5f * x * (1.0f + t);
}

template<int ACT>
__global__ __launch_bounds__(256) void sgemm_kernel(
    const float* __restrict__ A, const float* __restrict__ B,
    const float* __restrict__ Res, float* __restrict__ C,
    int M, int N, int K)
{
    constexpr int BM = 128, BN = 128, BK = 8, TM = 8, TN = 8;
    __shared__ float As[BK][BM];
    __shared__ float Bs[BK][BN];

    const int tid = threadIdx.x;
    const int tx = tid & 15;     // output col group
    const int ty = tid >> 4;     // output row group
    const int bm = blockIdx.y * BM;
    const int bn = blockIdx.x * BN;

    const int a_row = tid >> 1;          // 0..127
    const int a_col = (tid & 1) * 4;     // 0 or 4
    const int b_row = tid >> 5;          // 0..7
    const int b_col = (tid & 31) * 4;    // 0..124

    const float* Ab = A + (size_t)(bm + a_row) * K + a_col;
    const float* Bb = B + (size_t)b_row * N + bn + b_col;

    float acc[TM][TN];
    #pragma unroll
    for (int i = 0; i < TM; i++)
        #pragma unroll
        for (int j = 0; j < TN; j++) acc[i][j] = 0.0f;

    for (int k0 = 0; k0 < K; k0 += BK) {
        float4 av = *reinterpret_cast<const float4*>(Ab + k0);
        As[a_col+0][a_row] = av.x;
        As[a_col+1][a_row] = av.y;
        As[a_col+2][a_row] = av.z;
        As[a_col+3][a_row] = av.w;
        float4 bv = *reinterpret_cast<const float4*>(Bb + (size_t)k0 * N);
        *reinterpret_cast<float4*>(&Bs[b_row][b_col]) = bv;
        __syncthreads();

        #pragma unroll
        for (int kk = 0; kk < BK; kk++) {
            float ar[TM], br[TN];
            #pragma unroll
            for (int i = 0; i < TM; i++) ar[i] = As[kk][ty*TM + i];
            #pragma unroll
            for (int j = 0; j < TN; j++) br[j] = Bs[kk][tx*TN + j];
            #pragma unroll
            for (int i = 0; i < TM; i++)
                #pragma unroll
                for (int j = 0; j < TN; j++)
                    acc[i][j] = fmaf(ar[i], br[j], acc[i][j]);
        }
        __syncthreads();
    }

    #pragma unroll
    for (int i = 0; i < TM; i++) {
        const int r = bm + ty*TM + i;
        float* crow = C + (size_t)r * N + bn + tx*TN;
        const float* rrow = (ACT == 1) ? (Res + (size_t)r * N + bn + tx*TN) : nullptr;
        #pragma unroll
        for (int v4 = 0; v4 < 2; v4++) {
            float4 o;
            float vals[4];
            #pragma unroll
            for (int j = 0; j < 4; j++) {
                float v = acc[i][v4*4 + j];
                if (ACT == 2) v = gelu_tanh(v);
                vals[j] = v;
            }
            if (ACT == 1) {
                float4 rr = *reinterpret_cast<const float4*>(rrow + v4*4);
                vals[0] += rr.x; vals[1] += rr.y; vals[2] += rr.z; vals[3] += rr.w;
            }
            o.x = vals[0]; o.y = vals[1]; o.z = vals[2]; o.w = vals[3];
            *reinterpret_cast<float4*>(crow + v4*4) = o;
        }
    }
}

// ---------------- Flash attention (causal), BQ=BK=64, HD=128 ---------------
// Thread layout: 256 threads; tx = tid&15 (key/col groups), ty = tid>>4
// (query groups; rows ty*4..ty*4+3). Each thread owns 4x4 scores and a
// 4x8 output accumulator (cols tx + 16*cc).
#define QSTRIDE 132   // 128 + 4 pad; 132*4 bytes % 16 == 0 -> float4 ok
#define KSTRIDE 68    // 64 + 4 pad
#define PSTRIDE 68

__global__ __launch_bounds__(256) void flash_kernel(
    const float* __restrict__ Q, const float* __restrict__ K,
    const float* __restrict__ V, float* __restrict__ O)
{
    extern __shared__ float sm[];
    float* Qs = sm;                         // [64][132]
    float* Kt = Qs + 64*QSTRIDE;            // [128][68]  (d-major)
    float* Vs = Kt + 128*KSTRIDE;           // [64][132]
    float* Ps = Vs + 64*QSTRIDE;            // [64][68]

    const int tid = threadIdx.x;
    const int tx = tid & 15;
    const int ty = tid >> 4;
    const int bh = blockIdx.y;
    const int b  = bh >> 4;
    const int h  = bh & 15;
    const int qb = blockIdx.x;
    const size_t rowbase = (size_t)b * SEQ;
    const int colbase = h * HDIM;
    const float scale = 0.088388347648318447f;  // 1/sqrt(128)

    // load Q tile
    #pragma unroll
    for (int it = 0; it < 8; ++it) {
        int idx = it * 256 + tid;      // 0..2047
        int r  = idx >> 5;
        int c4 = (idx & 31) << 2;
        float4 qv = *reinterpret_cast<const float4*>(
            &Q[(rowbase + qb*64 + r) * HID + colbase + c4]);
        *reinterpret_cast<float4*>(&Qs[r*QSTRIDE + c4]) = qv;
    }

    float m[4], l[4], o[4][8];
    #pragma unroll
    for (int i = 0; i < 4; i++) {
        m[i] = -1e30f; l[i] = 0.0f;
        #pragma unroll
        for (int c = 0; c < 8; c++) o[i][c] = 0.0f;
    }

    for (int kb = 0; kb <= qb; ++kb) {
        __syncthreads();  // Qs ready (iter 0) / previous PV done
        // load K (transposed to d-major) and V
        #pragma unroll
        for (int it = 0; it < 8; ++it) {
            int idx = it * 256 + tid;
            int r  = idx >> 5;
            int c4 = (idx & 31) << 2;
            const size_t grow = (rowbase + kb*64 + r) * (size_t)HID + colbase + c4;
            float4 kv = *reinterpret_cast<const float4*>(&K[grow]);
            Kt[(c4+0)*KSTRIDE + r] = kv.x;
            Kt[(c4+1)*KSTRIDE + r] = kv.y;
            Kt[(c4+2)*KSTRIDE + r] = kv.z;
            Kt[(c4+3)*KSTRIDE + r] = kv.w;
            float4 vv = *reinterpret_cast<const float4*>(&V[grow]);
            *reinterpret_cast<float4*>(&Vs[r*QSTRIDE + c4]) = vv;
        }
        __syncthreads();

        // scores: rows ty*4+i, cols tx+16*jj
        float s[4][4];
        #pragma unroll
        for (int i = 0; i < 4; i++)
            #pragma unroll
            for (int jj = 0; jj < 4; jj++) s[i][jj] = 0.0f;

        #pragma unroll 4
        for (int d = 0; d < HDIM; ++d) {
            float kr[4];
            #pragma unroll
            for (int jj = 0; jj < 4; jj++) kr[jj] = Kt[d*KSTRIDE + tx + 16*jj];
            #pragma unroll
            for (int i = 0; i < 4; i++) {
                float qv = Qs[(ty*4 + i)*QSTRIDE + d];
                #pragma unroll
                for (int jj = 0; jj < 4; jj++)
                    s[i][jj] = fmaf(qv, kr[jj], s[i][jj]);
            }
        }

        const bool diag = (kb == qb);
        #pragma unroll
        for (int i = 0; i < 4; i++) {
            const int qg = qb*64 + ty*4 + i;
            float mx = -1e30f;
            #pragma unroll
            for (int jj = 0; jj < 4; jj++) {
                float v = s[i][jj] * scale;
                if (diag && (kb*64 + tx + 16*jj) > qg) v = -1e30f;
                s[i][jj] = v;
                mx = fmaxf(mx, v);
            }
            #pragma unroll
            for (int off = 8; off > 0; off >>= 1)
                mx = fmaxf(mx, __shfl_xor_sync(0xffffffffu, mx, off));
            float mnew = fmaxf(m[i], mx);
            float corr = __expf(m[i] - mnew);
            float rs = 0.0f;
            #pragma unroll
            for (int jj = 0; jj < 4; jj++) {
                float p = __expf(s[i][jj] - mnew);
                s[i][jj] = p;
                rs += p;
            }
            #pragma unroll
            for (int off = 8; off > 0; off >>= 1)
                rs += __shfl_xor_sync(0xffffffffu, rs, off);
            l[i] = l[i]*corr + rs;
            m[i] = mnew;
            #pragma unroll
            for (int c = 0; c < 8; c++) o[i][c] *= corr;
            #pragma unroll
            for (int jj = 0; jj < 4; jj++)
                Ps[(ty*4 + i)*PSTRIDE + tx + 16*jj] = s[i][jj];
        }
        __syncthreads();

        // PV accumulate
        #pragma unroll 4
        for (int j = 0; j < 64; ++j) {
            float vr[8];
            #pragma unroll
            for (int c = 0; c < 8; c++) vr[c] = Vs[j*QSTRIDE + tx + 16*c];
            #pragma unroll
            for (int i = 0; i < 4; i++) {
                float p = Ps[(ty*4 + i)*PSTRIDE + j];
                #pragma unroll
                for (int c = 0; c < 8; c++)
                    o[i][c] = fmaf(p, vr[c], o[i][c]);
            }
        }
    }

    #pragma unroll
    for (int i = 0; i < 4; i++) {
        float inv = 1.0f / l[i];
        const size_t r = rowbase + qb*64 + ty*4 + i;
        #pragma unroll
        for (int c = 0; c < 8; c++)
            O[r*HID + colbase + tx + 16*c] = o[i][c] * inv;
    }
}

// ---------------------------------------------------------------------------
extern "C" void kernel_launch(void* const* d_in, const int* in_sizes, int n_in,
                              void* d_out, int out_size)
{
    const float* x     = (const float*)d_in[0];
    // d_in[1] = mask (ignored; causal triu(k=1) applied analytically)
    const float* wq    = (const float*)d_in[2];
    const float* wk    = (const float*)d_in[3];
    const float* wv    = (const float*)d_in[4];
    const float* wo    = (const float*)d_in[5];
    const float* w_in  = (const float*)d_in[6];
    const float* w_out = (const float*)d_in[7];
    const float* ln1_g = (const float*)d_in[8];
    const float* ln1_b = (const float*)d_in[9];
    const float* ln2_g = (const float*)d_in[10];
    const float* ln2_b = (const float*)d_in[11];
    float* out = (float*)d_out;

    float *xn, *q, *k, *v, *att, *h, *hn, *ff;
    cudaGetSymbolAddress((void**)&xn,  g_xn);
    cudaGetSymbolAddress((void**)&q,   g_q);
    cudaGetSymbolAddress((void**)&k,   g_k);
    cudaGetSymbolAddress((void**)&v,   g_v);
    cudaGetSymbolAddress((void**)&att, g_att);
    cudaGetSymbolAddress((void**)&h,   g_h);
    cudaGetSymbolAddress((void**)&hn,  g_hn);
    cudaGetSymbolAddress((void**)&ff,  g_ff);

    const int smem_flash = (64*QSTRIDE + 128*KSTRIDE + 64*QSTRIDE + 64*PSTRIDE) * 4;
    cudaFuncSetAttribute(flash_kernel,
                         cudaFuncAttributeMaxDynamicSharedMemorySize, smem_flash);

    // 1. LN1
    ln_kernel<<<ROWS, 256>>>(x, ln1_g, ln1_b, xn);

    // 2. QKV projections
    dim3 gproj(HID/128, ROWS/128);
    sgemm_kernel<0><<<gproj, 256>>>(xn, wq, nullptr, q, ROWS, HID, HID);
    sgemm_kernel<0><<<gproj, 256>>>(xn, wk, nullptr, k, ROWS, HID, HID);
    sgemm_kernel<0><<<gproj, 256>>>(xn, wv, nullptr, v, ROWS, HID, HID);

    // 3. causal flash attention
    dim3 gattn(SEQ/64, BATCH*NHEAD);
    flash_kernel<<<gattn, 256, smem_flash>>>(q, k, v, att);

    // 4. output projection + residual
    sgemm_kernel<1><<<gproj, 256>>>(att, wo, x, h, ROWS, HID, HID);

    // 5. LN2
    ln_kernel<<<ROWS, 256>>>(h, ln2_g, ln2_b, hn);

    // 6. FFN up + GELU
    dim3 gff1(FFD/128, ROWS/128);
    sgemm_kernel<2><<<gff1, 256>>>(hn, w_in, nullptr, ff, ROWS, FFD, HID);

    // 7. FFN down + residual -> d_out
    dim3 gff2(HID/128, ROWS/128);
    sgemm_kernel<1><<<gff2, 256>>>(ff, w_out, h, out, ROWS, HID, FFD);
}

// round 4
// speedup vs baseline: 2.3338x; 2.3338x over previous
#include <cuda_runtime.h>
#include <cuda_fp16.h>
#include <math.h>
#include <cstdint>

#define BATCH 2
#define SEQ   2048
#define HID   2048
#define NHEAD 16
#define HDIM  128
#define FFD   8192
#define ROWS  (BATCH*SEQ)   // 4096

// ---------------- scratch ---------------------------------------------------
// fp32 buffers
__device__ float g_q [ROWS*HID];
__device__ float g_k [ROWS*HID];
__device__ float g_v [ROWS*HID];
__device__ float g_h [ROWS*HID];
// split-fp16 (hi/lo) activations
__device__ __half g_xnh[ROWS*HID];
__device__ __half g_xnl[ROWS*HID];
__device__ __half g_atth[ROWS*HID];
__device__ __half g_attl[ROWS*HID];
__device__ __half g_hnh[ROWS*HID];
__device__ __half g_hnl[ROWS*HID];
__device__ __half g_ffh[(size_t)ROWS*FFD];
__device__ __half g_ffl[(size_t)ROWS*FFD];
// split-fp16 weights
__device__ __half g_wqh[HID*HID];   __device__ __half g_wql[HID*HID];
__device__ __half g_wkh[HID*HID];   __device__ __half g_wkl[HID*HID];
__device__ __half g_wvh[HID*HID];   __device__ __half g_wvl[HID*HID];
__device__ __half g_woh[HID*HID];   __device__ __half g_wol[HID*HID];
__device__ __half g_winh[(size_t)HID*FFD];  __device__ __half g_winl[(size_t)HID*FFD];
__device__ __half g_wouth[(size_t)HID*FFD]; __device__ __half g_woutl[(size_t)HID*FFD];

// ============================ helpers ========================================
__device__ __forceinline__ uint32_t smem_u32(const void* p) {
    uint32_t a;
    asm("{ .reg .u64 t; cvta.to.shared.u64 t, %1; cvt.u32.u64 %0, t; }"
        : "=r"(a) : "l"(p));
    return a;
}
__device__ __forceinline__ void cp16(uint32_t dst, const void* src) {
    asm volatile("cp.async.cg.shared.global [%0], [%1], 16;" :: "r"(dst), "l"(src));
}
__device__ __forceinline__ void cp_commit() { asm volatile("cp.async.commit_group;"); }
template<int N> __device__ __forceinline__ void cp_wait() {
    asm volatile("cp.async.wait_group %0;" :: "n"(N));
}
__device__ __forceinline__ void ldsm_x4(uint32_t* r, uint32_t addr) {
    asm volatile("ldmatrix.sync.aligned.m8n8.x4.shared.b16 {%0,%1,%2,%3}, [%4];"
        : "=r"(r[0]), "=r"(r[1]), "=r"(r[2]), "=r"(r[3]) : "r"(addr));
}
__device__ __forceinline__ void ldsm_x4_t(uint32_t* r, uint32_t addr) {
    asm volatile("ldmatrix.sync.aligned.m8n8.x4.trans.shared.b16 {%0,%1,%2,%3}, [%4];"
        : "=r"(r[0]), "=r"(r[1]), "=r"(r[2]), "=r"(r[3]) : "r"(addr));
}
__device__ __forceinline__ void mma_f16(float* c, const uint32_t* a, const uint32_t* b) {
    asm volatile("mma.sync.aligned.m16n8k16.row.col.f32.f16.f16.f32 "
        "{%0,%1,%2,%3}, {%4,%5,%6,%7}, {%8,%9}, {%0,%1,%2,%3};"
        : "+f"(c[0]), "+f"(c[1]), "+f"(c[2]), "+f"(c[3])
        : "r"(a[0]), "r"(a[1]), "r"(a[2]), "r"(a[3]), "r"(b[0]), "r"(b[1]));
}
__device__ __forceinline__ float gelu_tanh(float x) {
    float x3 = x * x * x;
    float t  = tanhf(0.7978845608028654f * (x + 0.044715f * x3));
    return 0.5f * x * (1.0f + t);
}
__device__ __forceinline__ void split_val(float v, __half& hi, __half& lo) {
    hi = __float2half_rn(v);
    lo = __float2half_rn(v - __half2float(hi));
}

// ============================================================================
// split-fp16 tensor-core GEMM: C[M,N] = A[M,K] @ B[K,N] at ~fp32 accuracy.
// A given as (Ahi, Alo) fp16 row-major; B as (Bhi, Blo) fp16 row-major [K,N].
// Per k16 step: C += Ahi*Bhi + Ahi*Blo + Alo*Bhi  (3x mma.sync m16n8k16)
// ACT: 0 none -> Cf, 1 +Res -> Cf, 2 GELU -> (Chi, Clo) fp16 split
// ============================================================================
#define BM 128
#define BN 128
#define BKH 32          // k elements per stage
#define LDAH 40         // A smem stride (halves): 80B -> ldmatrix conflict-free
#define LDBH 136        // B smem stride (halves): 272B -> conflict-free
#define ASZH (BM*LDAH)  // 5120 halves
#define BSZH (BKH*LDBH) // 4352 halves
#define STG 3
#define STAGEH (2*ASZH + 2*BSZH)       // 18944 halves per stage
#define GEMM_SMEM (STG*STAGEH*2)       // 113664 bytes

template<int ACT>
__global__ __launch_bounds__(256) void tc_gemm(
    const __half* __restrict__ Ahi, const __half* __restrict__ Alo,
    const __half* __restrict__ Bhi, const __half* __restrict__ Blo,
    const float* __restrict__ Res, float* __restrict__ Cf,
    __half* __restrict__ Chi, __half* __restrict__ Clo,
    int N_, int K)
{
    extern __shared__ __align__(16) __half smem[];

    const int tid  = threadIdx.x;
    const int wid  = tid >> 5;
    const int lane = tid & 31;
    const int gid  = lane >> 2;
    const int tg   = lane & 3;
    const int wm   = wid & 3;       // 4 warps in m: 32 rows each
    const int wn   = wid >> 2;      // 2 warps in n: 64 cols each
    const int bm = blockIdx.y * BM;
    const int bn = blockIdx.x * BN;
    const int nK = K / BKH;

    // ldmatrix source addresses (per-lane)
    const int a_m = lane & 15;            // row within 16-row tile
    const int a_k = (lane >> 4) * 8;      // 0 or 8
    const int b_k = ((lane >> 3) & 1) * 8 + (lane & 7);
    const int b_n = (lane >> 4) * 8;      // 0 or 8

    auto load_stage = [&](int s, int kt) {
        const int k0 = kt * BKH;
        __half* Ah = smem + s*STAGEH;
        __half* Al = Ah + ASZH;
        __half* Bh = Al + ASZH;
        __half* Bl = Bh + BSZH;
        #pragma unroll
        for (int i = 0; i < 2; i++) {
            const int c  = tid + 256*i;
            const int ar = c >> 2, ak = (c & 3) << 3;
            cp16(smem_u32(&Ah[ar*LDAH + ak]), &Ahi[(size_t)(bm + ar)*K + k0 + ak]);
            cp16(smem_u32(&Al[ar*LDAH + ak]), &Alo[(size_t)(bm + ar)*K + k0 + ak]);
            const int bk = c >> 4, bnn = (c & 15) << 3;
            cp16(smem_u32(&Bh[bk*LDBH + bnn]), &Bhi[(size_t)(k0 + bk)*N_ + bn + bnn]);
            cp16(smem_u32(&Bl[bk*LDBH + bnn]), &Blo[(size_t)(k0 + bk)*N_ + bn + bnn]);
        }
        cp_commit();
    };

    float acc[2][8][4];
    #pragma unroll
    for (int mt = 0; mt < 2; mt++)
        #pragma unroll
        for (int nt = 0; nt < 8; nt++)
            #pragma unroll
            for (int r = 0; r < 4; r++) acc[mt][nt][r] = 0.0f;

    load_stage(0, 0);
    load_stage(1, 1);

    for (int kt = 0; kt < nK; kt++) {
        cp_wait<1>();
        __syncthreads();
        const int s = kt % STG;
        const __half* Ah = smem + s*STAGEH;
        const __half* Al = Ah + ASZH;
        const __half* Bh = Al + ASZH;
        const __half* Bl = Bh + BSZH;

        #pragma unroll
        for (int kk = 0; kk < 2; kk++) {
            uint32_t ah[2][4], al[2][4];
            #pragma unroll
            for (int mt = 0; mt < 2; mt++) {
                const int mrow = wm*32 + mt*16 + a_m;
                const int koff = kk*16 + a_k;
                ldsm_x4(ah[mt], smem_u32(&Ah[mrow*LDAH + koff]));
                ldsm_x4(al[mt], smem_u32(&Al[mrow*LDAH + koff]));
            }
            uint32_t bh[4][4], bl[4][4];
            #pragma unroll
            for (int ng = 0; ng < 4; ng++) {
                const int koff = kk*16 + b_k;
                const int noff = wn*64 + ng*16 + b_n;
                ldsm_x4_t(bh[ng], smem_u32(&Bh[koff*LDBH + noff]));
                ldsm_x4_t(bl[ng], smem_u32(&Bl[koff*LDBH + noff]));
            }
            #pragma unroll
            for (int mt = 0; mt < 2; mt++)
                #pragma unroll
                for (int nt = 0; nt < 8; nt++) {
                    const uint32_t* bhp = &bh[nt >> 1][(nt & 1) * 2];
                    const uint32_t* blp = &bl[nt >> 1][(nt & 1) * 2];
                    mma_f16(acc[mt][nt], ah[mt], bhp);   // hi*hi
                    mma_f16(acc[mt][nt], ah[mt], blp);   // hi*lo
                    mma_f16(acc[mt][nt], al[mt], bhp);   // lo*hi
                }
        }
        __syncthreads();
        if (kt + STG - 1 < nK)
            load_stage((kt + STG - 1) % STG, kt + STG - 1);
    }

    // ---- epilogue ----
    #pragma unroll
    for (int mt = 0; mt < 2; mt++) {
        #pragma unroll
        for (int half_ = 0; half_ < 2; half_++) {
            const int r = bm + wm*32 + mt*16 + gid + half_*8;
            #pragma unroll
            for (int nt = 0; nt < 8; nt++) {
                const int cc = bn + wn*64 + nt*8 + tg*2;
                float v0 = acc[mt][nt][half_*2 + 0];
                float v1 = acc[mt][nt][half_*2 + 1];
                if (ACT == 2) {
                    v0 = gelu_tanh(v0); v1 = gelu_tanh(v1);
                    __half h0, l0, h1, l1;
                    split_val(v0, h0, l0); split_val(v1, h1, l1);
                    *reinterpret_cast<__half2*>(&Chi[(size_t)r*N_ + cc]) = __halves2half2(h0, h1);
                    *reinterpret_cast<__half2*>(&Clo[(size_t)r*N_ + cc]) = __halves2half2(l0, l1);
                } else {
                    if (ACT == 1) {
                        const float2 rr = *reinterpret_cast<const float2*>(&Res[(size_t)r*N_ + cc]);
                        v0 += rr.x; v1 += rr.y;
                    }
                    float2 o; o.x = v0; o.y = v1;
                    *reinterpret_cast<float2*>(&Cf[(size_t)r*N_ + cc]) = o;
                }
            }
        }
    }
}

// ---------------- weight split: fp32 -> (hi, lo) fp16 -----------------------
__global__ void split_kernel(const float* __restrict__ in,
                             __half* __restrict__ hi, __half* __restrict__ lo,
                             int n4)
{
    const int i = blockIdx.x*blockDim.x + threadIdx.x;
    if (i >= n4) return;
    float4 v = reinterpret_cast<const float4*>(in)[i];
    __half h0,l0,h1,l1,h2,l2,h3,l3;
    split_val(v.x, h0, l0); split_val(v.y, h1, l1);
    split_val(v.z, h2, l2); split_val(v.w, h3, l3);
    reinterpret_cast<__half2*>(hi)[2*i+0] = __halves2half2(h0, h1);
    reinterpret_cast<__half2*>(hi)[2*i+1] = __halves2half2(h2, h3);
    reinterpret_cast<__half2*>(lo)[2*i+0] = __halves2half2(l0, l1);
    reinterpret_cast<__half2*>(lo)[2*i+1] = __halves2half2(l2, l3);
}

// ---------------- LayerNorm -> split fp16 outputs ---------------------------
__global__ void ln_kernel(const float* __restrict__ x,
                          const float* __restrict__ g,
                          const float* __restrict__ b,
                          __half* __restrict__ ohi, __half* __restrict__ olo)
{
    const int row = blockIdx.x;
    const int tid = threadIdx.x;
    const float* xr = x + (size_t)row * HID;

    float4 v0 = reinterpret_cast<const float4*>(xr)[tid];
    float4 v1 = reinterpret_cast<const float4*>(xr)[tid + 256];

    __shared__ float red[8];

    float s = v0.x+v0.y+v0.z+v0.w + v1.x+v1.y+v1.z+v1.w;
    #pragma unroll
    for (int o = 16; o > 0; o >>= 1) s += __shfl_xor_sync(0xffffffffu, s, o);
    if ((tid & 31) == 0) red[tid >> 5] = s;
    __syncthreads();
    float mu = (red[0]+red[1]+red[2]+red[3]+red[4]+red[5]+red[6]+red[7]) * (1.0f/HID);
    __syncthreads();

    float d0x=v0.x-mu, d0y=v0.y-mu, d0z=v0.z-mu, d0w=v0.w-mu;
    float d1x=v1.x-mu, d1y=v1.y-mu, d1z=v1.z-mu, d1w=v1.w-mu;
    float sq = d0x*d0x+d0y*d0y+d0z*d0z+d0w*d0w + d1x*d1x+d1y*d1y+d1z*d1z+d1w*d1w;
    #pragma unroll
    for (int o = 16; o > 0; o >>= 1) sq += __shfl_xor_sync(0xffffffffu, sq, o);
    if ((tid & 31) == 0) red[tid >> 5] = sq;
    __syncthreads();
    float var = (red[0]+red[1]+red[2]+red[3]+red[4]+red[5]+red[6]+red[7]) * (1.0f/HID);
    float rstd = rsqrtf(var + 1e-5f);

    float4 g0 = reinterpret_cast<const float4*>(g)[tid];
    float4 g1 = reinterpret_cast<const float4*>(g)[tid + 256];
    float4 b0 = reinterpret_cast<const float4*>(b)[tid];
    float4 b1 = reinterpret_cast<const float4*>(b)[tid + 256];

    float o0[4] = { d0x*rstd*g0.x + b0.x, d0y*rstd*g0.y + b0.y,
                    d0z*rstd*g0.z + b0.z, d0w*rstd*g0.w + b0.w };
    float o1[4] = { d1x*rstd*g1.x + b1.x, d1y*rstd*g1.y + b1.y,
                    d1z*rstd*g1.z + b1.z, d1w*rstd*g1.w + b1.w };

    const size_t base = (size_t)row * HID;
    __half h[4], l[4];
    #pragma unroll
    for (int j = 0; j < 4; j++) split_val(o0[j], h[j], l[j]);
    reinterpret_cast<__half2*>(ohi + base)[tid*2+0] = __halves2half2(h[0], h[1]);
    reinterpret_cast<__half2*>(ohi + base)[tid*2+1] = __halves2half2(h[2], h[3]);
    reinterpret_cast<__half2*>(olo + base)[tid*2+0] = __halves2half2(l[0], l[1]);
    reinterpret_cast<__half2*>(olo + base)[tid*2+1] = __halves2half2(l[2], l[3]);
    #pragma unroll
    for (int j = 0; j < 4; j++) split_val(o1[j], h[j], l[j]);
    reinterpret_cast<__half2*>(ohi + base)[(tid+256)*2+0] = __halves2half2(h[0], h[1]);
    reinterpret_cast<__half2*>(ohi + base)[(tid+256)*2+1] = __halves2half2(h[2], h[3]);
    reinterpret_cast<__half2*>(olo + base)[(tid+256)*2+0] = __halves2half2(l[0], l[1]);
    reinterpret_cast<__half2*>(olo + base)[(tid+256)*2+1] = __halves2half2(l[2], l[3]);
}

// ---------------- Flash attention (causal, fp32) -> split fp16 out ----------
#define QSTRIDE 132
#define KSTRIDE 68
#define PSTRIDE 68

__global__ __launch_bounds__(256) void flash_kernel(
    const float* __restrict__ Q, const float* __restrict__ K,
    const float* __restrict__ V,
    __half* __restrict__ Ohi, __half* __restrict__ Olo)
{
    extern __shared__ float sm[];
    float* Qs = sm;
    float* Kt = Qs + 64*QSTRIDE;
    float* Vs = Kt + 128*KSTRIDE;
    float* Ps = Vs + 64*QSTRIDE;

    const int tid = threadIdx.x;
    const int tx = tid & 15;
    const int ty = tid >> 4;
    const int bh = blockIdx.y;
    const int b  = bh >> 4;
    const int h  = bh & 15;
    const int qb = blockIdx.x;
    const size_t rowbase = (size_t)b * SEQ;
    const int colbase = h * HDIM;
    const float scale = 0.088388347648318447f;

    #pragma unroll
    for (int it = 0; it < 8; ++it) {
        int idx = it * 256 + tid;
        int r  = idx >> 5;
        int c4 = (idx & 31) << 2;
        float4 qv = *reinterpret_cast<const float4*>(
            &Q[(rowbase + qb*64 + r) * HID + colbase + c4]);
        *reinterpret_cast<float4*>(&Qs[r*QSTRIDE + c4]) = qv;
    }

    float m[4], l[4], o[4][8];
    #pragma unroll
    for (int i = 0; i < 4; i++) {
        m[i] = -1e30f; l[i] = 0.0f;
        #pragma unroll
        for (int c = 0; c < 8; c++) o[i][c] = 0.0f;
    }

    for (int kb = 0; kb <= qb; ++kb) {
        __syncthreads();
        #pragma unroll
        for (int it = 0; it < 8; ++it) {
            int idx = it * 256 + tid;
            int r  = idx >> 5;
            int c4 = (idx & 31) << 2;
            const size_t grow = (rowbase + kb*64 + r) * (size_t)HID + colbase + c4;
            float4 kv = *reinterpret_cast<const float4*>(&K[grow]);
            Kt[(c4+0)*KSTRIDE + r] = kv.x;
            Kt[(c4+1)*KSTRIDE + r] = kv.y;
            Kt[(c4+2)*KSTRIDE + r] = kv.z;
            Kt[(c4+3)*KSTRIDE + r] = kv.w;
            float4 vv = *reinterpret_cast<const float4*>(&V[grow]);
            *reinterpret_cast<float4*>(&Vs[r*QSTRIDE + c4]) = vv;
        }
        __syncthreads();

        float s[4][4];
        #pragma unroll
        for (int i = 0; i < 4; i++)
            #pragma unroll
            for (int jj = 0; jj < 4; jj++) s[i][jj] = 0.0f;

        #pragma unroll 4
        for (int d = 0; d < HDIM; ++d) {
            float kr[4];
            #pragma unroll
            for (int jj = 0; jj < 4; jj++) kr[jj] = Kt[d*KSTRIDE + tx + 16*jj];
            #pragma unroll
            for (int i = 0; i < 4; i++) {
                float qv = Qs[(ty*4 + i)*QSTRIDE + d];
                #pragma unroll
                for (int jj = 0; jj < 4; jj++)
                    s[i][jj] = fmaf(qv, kr[jj], s[i][jj]);
            }
        }

        const bool diag = (kb == qb);
        #pragma unroll
        for (int i = 0; i < 4; i++) {
            const int qg = qb*64 + ty*4 + i;
            float mx = -1e30f;
            #pragma unroll
            for (int jj = 0; jj < 4; jj++) {
                float v = s[i][jj] * scale;
                if (diag && (kb*64 + tx + 16*jj) > qg) v = -1e30f;
                s[i][jj] = v;
                mx = fmaxf(mx, v);
            }
            #pragma unroll
            for (int off = 8; off > 0; off >>= 1)
                mx = fmaxf(mx, __shfl_xor_sync(0xffffffffu, mx, off));
            float mnew = fmaxf(m[i], mx);
            float corr = __expf(m[i] - mnew);
            float rs = 0.0f;
            #pragma unroll
            for (int jj = 0; jj < 4; jj++) {
                float p = __expf(s[i][jj] - mnew);
                s[i][jj] = p;
                rs += p;
            }
            #pragma unroll
            for (int off = 8; off > 0; off >>= 1)
                rs += __shfl_xor_sync(0xffffffffu, rs, off);
            l[i] = l[i]*corr + rs;
            m[i] = mnew;
            #pragma unroll
            for (int c = 0; c < 8; c++) o[i][c] *= corr;
            #pragma unroll
            for (int jj = 0; jj < 4; jj++)
                Ps[(ty*4 + i)*PSTRIDE + tx + 16*jj] = s[i][jj];
        }
        __syncthreads();

        #pragma unroll 4
        for (int j = 0; j < 64; ++j) {
            float vr[8];
            #pragma unroll
            for (int c = 0; c < 8; c++) vr[c] = Vs[j*QSTRIDE + tx + 16*c];
            #pragma unroll
            for (int i = 0; i < 4; i++) {
                float p = Ps[(ty*4 + i)*PSTRIDE + j];
                #pragma unroll
                for (int c = 0; c < 8; c++)
                    o[i][c] = fmaf(p, vr[c], o[i][c]);
            }
        }
    }

    #pragma unroll
    for (int i = 0; i < 4; i++) {
        float inv = 1.0f / l[i];
        const size_t r = rowbase + qb*64 + ty*4 + i;
        #pragma unroll
        for (int c = 0; c < 8; c++) {
            float v = o[i][c] * inv;
            __half hh, ll;
            split_val(v, hh, ll);
            Ohi[r*HID + colbase + tx + 16*c] = hh;
            Olo[r*HID + colbase + tx + 16*c] = ll;
        }
    }
}

// ============================ host side =====================================
extern "C" void kernel_launch(void* const* d_in, const int* in_sizes, int n_in,
                              void* d_out, int out_size)
{
    const float* x     = (const float*)d_in[0];
    // d_in[1] = mask (ignored; causal triu(k=1) applied analytically)
    const float* wq    = (const float*)d_in[2];
    const float* wk    = (const float*)d_in[3];
    const float* wv    = (const float*)d_in[4];
    const float* wo    = (const float*)d_in[5];
    const float* w_in  = (const float*)d_in[6];
    const float* w_out = (const float*)d_in[7];
    const float* ln1_g = (const float*)d_in[8];
    const float* ln1_b = (const float*)d_in[9];
    const float* ln2_g = (const float*)d_in[10];
    const float* ln2_b = (const float*)d_in[11];
    float* out = (float*)d_out;

    float *q, *k, *v, *h;
    __half *xnh,*xnl,*atth,*attl,*hnh,*hnl,*ffh,*ffl;
    __half *wqh,*wql,*wkh,*wkl,*wvh,*wvl,*woh,*wol,*winh,*winl,*wouth,*woutl;
    cudaGetSymbolAddress((void**)&q,  g_q);
    cudaGetSymbolAddress((void**)&k,  g_k);
    cudaGetSymbolAddress((void**)&v,  g_v);
    cudaGetSymbolAddress((void**)&h,  g_h);
    cudaGetSymbolAddress((void**)&xnh, g_xnh);   cudaGetSymbolAddress((void**)&xnl, g_xnl);
    cudaGetSymbolAddress((void**)&atth, g_atth); cudaGetSymbolAddress((void**)&attl, g_attl);
    cudaGetSymbolAddress((void**)&hnh, g_hnh);   cudaGetSymbolAddress((void**)&hnl, g_hnl);
    cudaGetSymbolAddress((void**)&ffh, g_ffh);   cudaGetSymbolAddress((void**)&ffl, g_ffl);
    cudaGetSymbolAddress((void**)&wqh, g_wqh);   cudaGetSymbolAddress((void**)&wql, g_wql);
    cudaGetSymbolAddress((void**)&wkh, g_wkh);   cudaGetSymbolAddress((void**)&wkl, g_wkl);
    cudaGetSymbolAddress((void**)&wvh, g_wvh);   cudaGetSymbolAddress((void**)&wvl, g_wvl);
    cudaGetSymbolAddress((void**)&woh, g_woh);   cudaGetSymbolAddress((void**)&wol, g_wol);
    cudaGetSymbolAddress((void**)&winh, g_winh); cudaGetSymbolAddress((void**)&winl, g_winl);
    cudaGetSymbolAddress((void**)&wouth, g_wouth); cudaGetSymbolAddress((void**)&woutl, g_woutl);

    cudaFuncSetAttribute(tc_gemm<0>, cudaFuncAttributeMaxDynamicSharedMemorySize, GEMM_SMEM);
    cudaFuncSetAttribute(tc_gemm<1>, cudaFuncAttributeMaxDynamicSharedMemorySize, GEMM_SMEM);
    cudaFuncSetAttribute(tc_gemm<2>, cudaFuncAttributeMaxDynamicSharedMemorySize, GEMM_SMEM);
    const int smem_flash = (64*QSTRIDE + 128*KSTRIDE + 64*QSTRIDE + 64*PSTRIDE) * 4;
    cudaFuncSetAttribute(flash_kernel, cudaFuncAttributeMaxDynamicSharedMemorySize, smem_flash);

    // 0. split weights to fp16 (hi, lo)
    {
        const int t = 256;
        split_kernel<<<(HID*HID/4 + t-1)/t, t>>>(wq, wqh, wql, HID*HID/4);
        split_kernel<<<(HID*HID/4 + t-1)/t, t>>>(wk, wkh, wkl, HID*HID/4);
        split_kernel<<<(HID*HID/4 + t-1)/t, t>>>(wv, wvh, wvl, HID*HID/4);
        split_kernel<<<(HID*HID/4 + t-1)/t, t>>>(wo, woh, wol, HID*HID/4);
        split_kernel<<<(HID*FFD/4 + t-1)/t, t>>>(w_in,  winh,  winl,  HID*FFD/4);
        split_kernel<<<(HID*FFD/4 + t-1)/t, t>>>(w_out, wouth, woutl, HID*FFD/4);
    }

    // 1. LN1 -> split
    ln_kernel<<<ROWS, 256>>>(x, ln1_g, ln1_b, xnh, xnl);

    // 2. QKV projections
    dim3 gproj(HID/BN, ROWS/BM);
    tc_gemm<0><<<gproj, 256, GEMM_SMEM>>>(xnh, xnl, wqh, wql, nullptr, q, nullptr, nullptr, HID, HID);
    tc_gemm<0><<<gproj, 256, GEMM_SMEM>>>(xnh, xnl, wkh, wkl, nullptr, k, nullptr, nullptr, HID, HID);
    tc_gemm<0><<<gproj, 256, GEMM_SMEM>>>(xnh, xnl, wvh, wvl, nullptr, v, nullptr, nullptr, HID, HID);

    // 3. causal flash attention -> split att
    dim3 gattn(SEQ/64, BATCH*NHEAD);
    flash_kernel<<<gattn, 256, smem_flash>>>(q, k, v, atth, attl);

    // 4. output projection + residual -> h (fp32)
    tc_gemm<1><<<gproj, 256, GEMM_SMEM>>>(atth, attl, woh, wol, x, h, nullptr, nullptr, HID, HID);

    // 5. LN2 -> split
    ln_kernel<<<ROWS, 256>>>(h, ln2_g, ln2_b, hnh, hnl);

    // 6. FFN up + GELU -> split ff
    dim3 gff1(FFD/BN, ROWS/BM);
    tc_gemm<2><<<gff1, 256, GEMM_SMEM>>>(hnh, hnl, winh, winl, nullptr, nullptr, ffh, ffl, FFD, HID);

    // 7. FFN down + residual -> d_out (fp32)
    dim3 gff2(HID/BN, ROWS/BM);
    tc_gemm<1><<<gff2, 256, GEMM_SMEM>>>(ffh, ffl, wouth, woutl, h, out, nullptr, nullptr, HID, FFD);
}